// round 4
// baseline (speedup 1.0000x reference)
#include <cuda_runtime.h>
#include <math.h>

// Problem: DYAN FISTA sparse coding.
//   x: [2, 36, 20480] f32, Drr/Dtheta: [40] f32, T=36 (ignored scalar input)
//   out: [2, 161, 20480] f32
//
// Strategy:
//   - build dictionary D[36][161] (padded to 168 cols) + linv/lam in a tiny
//     setup kernel (one block)
//   - persistent FISTA kernel: each CTA owns 96 columns (48 f32-pairs),
//     keeps y / DtY / V / D in SMEM and x_old in registers, runs all 100
//     iterations with zero HBM traffic in the loop.
//   - A@y+DtY factored as y - linv*D^T(D y) + DtY  (2.24x fewer FLOPs than
//     the 161x161 matvec).
//   - all FMAs are packed fp32 pairs via PTX fma.rn.f32x2 (full-rate fp32
//     on sm_103a; scalar FFMA is half-rate).

#define T36    36
#define KREAL  161
#define KP     168     // K padded to 21*8 for phase-2 k-tiling
#define NPAIR  48      // column pairs per CTA
#define NCOL   96      // columns per CTA
#define FDIM   20480
#define TOTCOL 40960   // 2 * 20480
#define NITER  100
#define NTHREADS 256

typedef unsigned long long ull;

// ---------------- device scratch (no allocations allowed) ----------------
__device__ float g_D[T36 * KP];   // normalized dictionary, row-major [t][k], padded cols zero
__device__ float g_consts[2];     // {linv, lam}

// ---------------- packed f32x2 helpers ----------------
__device__ __forceinline__ void fma2(ull &d, ull a, ull b) {
    asm("fma.rn.f32x2 %0, %1, %2, %0;" : "+l"(d) : "l"(a), "l"(b));
}
__device__ __forceinline__ ull dup2(float x) {
    ull r; unsigned u = __float_as_uint(x);
    asm("mov.b64 %0, {%1, %1};" : "=l"(r) : "r"(u));
    return r;
}
__device__ __forceinline__ ull pack2(float a, float b) {
    ull r;
    asm("mov.b64 %0, {%1, %2};" : "=l"(r) : "f"(a), "f"(b));
    return r;
}
__device__ __forceinline__ float2 unpack2(ull v) {
    float2 r;
    asm("mov.b64 {%0, %1}, %2;" : "=f"(r.x), "=f"(r.y) : "l"(v));
    return r;
}

// =====================================================================
// Setup: build normalized dictionary + linv = 1/||D^T D||_F, lam = 0.1*linv
// =====================================================================
__global__ void dyan_setup_kernel(const float* __restrict__ Drr,
                                  const float* __restrict__ Dtheta)
{
    __shared__ float  sDloc[T36 * KP];
    __shared__ double sred[NTHREADS];
    const int tid = threadIdx.x;

    for (int i = tid; i < T36 * KP; i += NTHREADS) sDloc[i] = 0.f;
    __syncthreads();

    for (int k = tid; k < KREAL; k += NTHREADS) {
        float col[T36];
        if (k == 0) {
            #pragma unroll
            for (int t = 0; t < T36; ++t) col[t] = 1.f;
        } else {
            const int grp = (k - 1) / 40;      // 0:rc 1:src 2:rs 3:srs
            const int n   = (k - 1) % 40;
            const float r  = Drr[n];
            const float th = Dtheta[n];
            for (int t = 0; t < T36; ++t) {
                float ri   = powf(r, (float)t);
                float base = (grp < 2) ? cosf((float)t * th) : sinf((float)t * th);
                float v = ri * base;
                if ((grp & 1) && (t & 1)) v = -v;   // (-1)^t on odd groups
                col[t] = v;
            }
        }
        float ss = 0.f;
        for (int t = 0; t < T36; ++t) ss += col[t] * col[t];
        float g = sqrtf(ss);
        if (g == 0.f) g = sqrtf((float)T36);
        for (int t = 0; t < T36; ++t) sDloc[t * KP + k] = col[t] / g;
    }
    __syncthreads();

    // Frobenius norm of D^T D
    double acc = 0.0;
    for (int idx = tid; idx < KREAL * KREAL; idx += NTHREADS) {
        const int i = idx / KREAL, j = idx % KREAL;
        float d = 0.f;
        for (int t = 0; t < T36; ++t) d += sDloc[t * KP + i] * sDloc[t * KP + j];
        acc += (double)d * (double)d;
    }
    sred[tid] = acc;
    __syncthreads();
    for (int s = NTHREADS / 2; s > 0; s >>= 1) {
        if (tid < s) sred[tid] += sred[tid + s];
        __syncthreads();
    }
    if (tid == 0) {
        const float fro = (float)sqrt(sred[0]);
        g_consts[0] = 1.f / fro;          // linv
        g_consts[1] = 0.1f / fro;         // lam = lambd * linv
    }
    for (int i = tid; i < T36 * KP; i += NTHREADS) g_D[i] = sDloc[i];
}

// =====================================================================
// Main persistent FISTA kernel
//   SMEM: sY[KP][48] u64, sDtY[KP][48] u64, sV[36][48] u64, sD[36][KP] f32
//   Phase1 (tid<144):  V = D @ Y          (3 t-rows x 4 pairs / thread)
//   Phase2 (tid<252):  S = D^T @ V + epilogue (8 k-rows x 4 pairs / thread)
//   x_old stays in the phase-2 thread's registers across all iterations.
// =====================================================================
__global__ void __launch_bounds__(NTHREADS, 1)
dyan_fista_kernel(const float* __restrict__ x, float* __restrict__ out)
{
    extern __shared__ unsigned char smraw[];
    ull*   sY   = (ull*)smraw;            // [KP][NPAIR]
    ull*   sDtY = sY   + KP  * NPAIR;     // [KP][NPAIR]
    ull*   sV   = sDtY + KP  * NPAIR;     // [T36][NPAIR]
    float* sD   = (float*)(sV + T36 * NPAIR); // [T36][KP]

    const int tid     = threadIdx.x;
    const int colBase = blockIdx.x * NCOL;
    const float linv = g_consts[0];
    const float lam  = g_consts[1];

    // ---- load D and the Y tile (Y tile temporarily parked in sV) ----
    for (int i = tid; i < T36 * KP; i += NTHREADS) sD[i] = g_D[i];
    for (int i = tid; i < T36 * NPAIR; i += NTHREADS) {
        const int t = i / NPAIR, p = i % NPAIR;
        const int c0 = colBase + 2 * p;
        ull v = 0ull;
        if (c0 < TOTCOL) {
            const int b = c0 / FDIM, f = c0 % FDIM;
            const float2 yv = *(const float2*)(x + ((size_t)b * T36 + t) * FDIM + f);
            v = pack2(yv.x, yv.y);
        }
        sV[i] = v;
    }
    for (int i = tid; i < KP * NPAIR; i += NTHREADS) sY[i] = 0ull;
    __syncthreads();

    const int  kt    = tid % 21;          // k-tile: rows 8kt..8kt+7
    const int  pt    = tid / 21;          // pair-tile: pairs 4pt..4pt+3
    const bool p2act = (tid < 252);

    // ---- DtY = linv * D^T @ Ytile  (phase-2 shaped GEMM, done once) ----
    if (p2act) {
        ull acc[8][4] = {};
        #pragma unroll 6
        for (int kk = 0; kk < T36; ++kk) {
            const float* arow = sD + kk * KP + 8 * kt;
            const float4 a03 = *(const float4*)(arow);
            const float4 a47 = *(const float4*)(arow + 4);
            const ull* brow = sV + (size_t)kk * NPAIR + 4 * pt;
            const ulonglong2 b01 = *(const ulonglong2*)(brow);
            const ulonglong2 b23 = *(const ulonglong2*)(brow + 2);
            const float as[8] = {a03.x, a03.y, a03.z, a03.w, a47.x, a47.y, a47.z, a47.w};
            #pragma unroll
            for (int i = 0; i < 8; ++i) {
                const ull ad = dup2(as[i]);
                fma2(acc[i][0], ad, b01.x);
                fma2(acc[i][1], ad, b01.y);
                fma2(acc[i][2], ad, b23.x);
                fma2(acc[i][3], ad, b23.y);
            }
        }
        #pragma unroll
        for (int i = 0; i < 8; ++i) {
            const int k = 8 * kt + i;                 // up to 167; padded rows are zero
            ull* drow = sDtY + (size_t)k * NPAIR + 4 * pt;
            #pragma unroll
            for (int j = 0; j < 4; ++j) {
                const float2 s = unpack2(acc[i][j]);
                drow[j] = pack2(s.x * linv, s.y * linv);
            }
        }
    }

    ull xold[8][4] = {};       // x_old in registers, fixed ownership
    float tcur = 1.f;
    __syncthreads();           // sDtY done; sV free to be reused as V

    const int  mt    = tid % 12;          // phase1: rows 3mt..3mt+2
    const int  p1    = tid / 12;          // phase1: pairs 4p1..4p1+3
    const bool p1act = (tid < 144);

    for (int it = 0; it < NITER; ++it) {
        // -------- phase 1: V = D @ Y --------
        if (p1act) {
            ull vac[3][4] = {};
            #pragma unroll 7
            for (int kk = 0; kk < KREAL; ++kk) {
                const float a0 = sD[(3 * mt + 0) * KP + kk];
                const float a1 = sD[(3 * mt + 1) * KP + kk];
                const float a2 = sD[(3 * mt + 2) * KP + kk];
                const ull* brow = sY + (size_t)kk * NPAIR + 4 * p1;
                const ulonglong2 b01 = *(const ulonglong2*)(brow);
                const ulonglong2 b23 = *(const ulonglong2*)(brow + 2);
                const ull d0 = dup2(a0), d1 = dup2(a1), d2 = dup2(a2);
                fma2(vac[0][0], d0, b01.x); fma2(vac[0][1], d0, b01.y);
                fma2(vac[0][2], d0, b23.x); fma2(vac[0][3], d0, b23.y);
                fma2(vac[1][0], d1, b01.x); fma2(vac[1][1], d1, b01.y);
                fma2(vac[1][2], d1, b23.x); fma2(vac[1][3], d1, b23.y);
                fma2(vac[2][0], d2, b01.x); fma2(vac[2][1], d2, b01.y);
                fma2(vac[2][2], d2, b23.x); fma2(vac[2][3], d2, b23.y);
            }
            #pragma unroll
            for (int i = 0; i < 3; ++i) {
                ull* vrow = sV + (size_t)(3 * mt + i) * NPAIR + 4 * p1;
                ulonglong2 w01; w01.x = vac[i][0]; w01.y = vac[i][1];
                ulonglong2 w23; w23.x = vac[i][2]; w23.y = vac[i][3];
                *(ulonglong2*)(vrow)     = w01;
                *(ulonglong2*)(vrow + 2) = w23;
            }
        }
        __syncthreads();

        // FISTA momentum scalars (identical in every thread)
        const float tnext = 0.5f * (1.f + sqrtf(fmaf(4.f * tcur, tcur, 1.f)));
        const float tt = (tcur - 1.f) / tnext;
        tcur = tnext;

        // -------- phase 2: S = D^T @ V, fused shrink + momentum --------
        if (p2act) {
            ull acc[8][4] = {};
            #pragma unroll 6
            for (int kk = 0; kk < T36; ++kk) {
                const float* arow = sD + kk * KP + 8 * kt;
                const float4 a03 = *(const float4*)(arow);
                const float4 a47 = *(const float4*)(arow + 4);
                const ull* brow = sV + (size_t)kk * NPAIR + 4 * pt;
                const ulonglong2 b01 = *(const ulonglong2*)(brow);
                const ulonglong2 b23 = *(const ulonglong2*)(brow + 2);
                const float as[8] = {a03.x, a03.y, a03.z, a03.w, a47.x, a47.y, a47.z, a47.w};
                #pragma unroll
                for (int i = 0; i < 8; ++i) {
                    const ull ad = dup2(as[i]);
                    fma2(acc[i][0], ad, b01.x);
                    fma2(acc[i][1], ad, b01.y);
                    fma2(acc[i][2], ad, b23.x);
                    fma2(acc[i][3], ad, b23.y);
                }
            }
            #pragma unroll
            for (int i = 0; i < 8; ++i) {
                const int k = 8 * kt + i;
                if (k < KREAL) {
                    ull* yrow = sY + (size_t)k * NPAIR + 4 * pt;
                    const ull* drow = sDtY + (size_t)k * NPAIR + 4 * pt;
                    const ulonglong2 y01 = *(const ulonglong2*)(yrow);
                    const ulonglong2 y23 = *(const ulonglong2*)(yrow + 2);
                    const ulonglong2 t01 = *(const ulonglong2*)(drow);
                    const ulonglong2 t23 = *(const ulonglong2*)(drow + 2);
                    const ull yv[4] = {y01.x, y01.y, y23.x, y23.y};
                    const ull dv[4] = {t01.x, t01.y, t23.x, t23.y};
                    ull ynew[4];
                    #pragma unroll
                    for (int j = 0; j < 4; ++j) {
                        const float2 s  = unpack2(acc[i][j]);
                        const float2 y2 = unpack2(yv[j]);
                        const float2 d2 = unpack2(dv[j]);
                        // r = y - linv * (DtD y) + DtY
                        const float r0 = fmaf(-linv, s.x, y2.x) + d2.x;
                        const float r1 = fmaf(-linv, s.y, y2.y) + d2.y;
                        // softshrink
                        const float x0 = copysignf(fmaxf(fabsf(r0) - lam, 0.f), r0);
                        const float x1 = copysignf(fmaxf(fabsf(r1) - lam, 0.f), r1);
                        // y_new = x_new + tt*(x_new - x_old)
                        const float2 xo = unpack2(xold[i][j]);
                        const float yn0 = fmaf(tt, x0 - xo.x, x0);
                        const float yn1 = fmaf(tt, x1 - xo.y, x1);
                        xold[i][j] = pack2(x0, x1);
                        ynew[j] = pack2(yn0, yn1);
                    }
                    ulonglong2 w01; w01.x = ynew[0]; w01.y = ynew[1];
                    ulonglong2 w23; w23.x = ynew[2]; w23.y = ynew[3];
                    *(ulonglong2*)(yrow)     = w01;
                    *(ulonglong2*)(yrow + 2) = w23;
                }
            }
        }
        __syncthreads();
    }

    // ---- write final x (= x_old after the last iteration) ----
    if (p2act) {
        #pragma unroll
        for (int i = 0; i < 8; ++i) {
            const int k = 8 * kt + i;
            if (k < KREAL) {
                #pragma unroll
                for (int j = 0; j < 4; ++j) {
                    const int c0 = colBase + 2 * (4 * pt + j);
                    if (c0 < TOTCOL) {
                        const int b = c0 / FDIM, f = c0 % FDIM;
                        *(float2*)(out + ((size_t)b * KREAL + k) * FDIM + f) = unpack2(xold[i][j]);
                    }
                }
            }
        }
    }
}

// =====================================================================
extern "C" void kernel_launch(void* const* d_in, const int* in_sizes, int n_in,
                              void* d_out, int out_size)
{
    const float* x   = (const float*)d_in[0];
    const float* drr = (const float*)d_in[1];
    const float* dth = (const float*)d_in[2];
    float* out = (float*)d_out;
    (void)in_sizes; (void)n_in; (void)out_size;

    const size_t smem = (size_t)(KP * NPAIR * 2 + T36 * NPAIR) * sizeof(ull)
                      + (size_t)(T36 * KP) * sizeof(float);   // 167,040 B

    cudaFuncSetAttribute(dyan_fista_kernel,
                         cudaFuncAttributeMaxDynamicSharedMemorySize, (int)smem);

    dyan_setup_kernel<<<1, NTHREADS>>>(drr, dth);

    const int grid = (TOTCOL + NCOL - 1) / NCOL;   // 427
    dyan_fista_kernel<<<grid, NTHREADS, smem>>>(x, out);
}

// round 8
// speedup vs baseline: 1.6339x; 1.6339x over previous
#include <cuda_runtime.h>
#include <math.h>

// DYAN FISTA sparse coding, fully SMEM-resident persistent iteration.
//   x: [2, 36, 20480] f32; Drr/Dtheta: [40] f32; out: [2, 161, 20480] f32
//
// Round-6: identical structure to round 4, with the alignment bug fixed:
//   SYS (row stride of sY/sDtY/sV in ull) 49 -> 50 so every ulonglong2
//   access is 16-byte aligned. Row delta = 100 words = 4 mod 32 banks, so
//   consecutive-kt lanes still stripe across disjoint bank quads.

#define T36    36
#define TPACK  20      // packed (t,t+1) rows incl pad to t=40
#define KREAL  161
#define KP     168     // padded K (21*8)
#define NPAIR  48      // column pairs per CTA (96 columns)
#define NCOL   96
#define FDIM   20480
#define TOTCOL 40960
#define NITER  100
#define NTHREADS 256
#define SYS    50      // EVEN row stride (ull) -> 16B alignment; 100 words % 32 = 4

typedef unsigned long long ull;

// ---------------- device scratch ----------------
__device__ float g_D[T36 * KP];   // normalized dictionary [t][k], pad cols zero
__device__ float g_consts[2];     // {linv, lam}

// ---------------- packed f32x2 helpers ----------------
__device__ __forceinline__ void fma2(ull &d, ull a, ull b) {
    asm("fma.rn.f32x2 %0, %1, %2, %0;" : "+l"(d) : "l"(a), "l"(b));
}
__device__ __forceinline__ ull dup2(float x) {
    ull r; unsigned u = __float_as_uint(x);
    asm("mov.b64 %0, {%1, %1};" : "=l"(r) : "r"(u));
    return r;
}
__device__ __forceinline__ ull pack2(float a, float b) {
    ull r;
    asm("mov.b64 %0, {%1, %2};" : "=l"(r) : "f"(a), "f"(b));
    return r;
}
__device__ __forceinline__ float2 unpack2(ull v) {
    float2 r;
    asm("mov.b64 {%0, %1}, %2;" : "=f"(r.x), "=f"(r.y) : "l"(v));
    return r;
}

// =====================================================================
// Setup: build normalized dictionary + linv = 1/||D^T D||_F, lam = 0.1*linv
// =====================================================================
__global__ void dyan_setup_kernel(const float* __restrict__ Drr,
                                  const float* __restrict__ Dtheta)
{
    __shared__ float  sDloc[T36 * KP];
    __shared__ double sred[NTHREADS];
    const int tid = threadIdx.x;

    for (int i = tid; i < T36 * KP; i += NTHREADS) sDloc[i] = 0.f;
    __syncthreads();

    for (int k = tid; k < KREAL; k += NTHREADS) {
        float col[T36];
        if (k == 0) {
            #pragma unroll
            for (int t = 0; t < T36; ++t) col[t] = 1.f;
        } else {
            const int grp = (k - 1) / 40;      // 0:rc 1:src 2:rs 3:srs
            const int n   = (k - 1) % 40;
            const float r  = Drr[n];
            const float th = Dtheta[n];
            for (int t = 0; t < T36; ++t) {
                float ri   = powf(r, (float)t);
                float base = (grp < 2) ? cosf((float)t * th) : sinf((float)t * th);
                float v = ri * base;
                if ((grp & 1) && (t & 1)) v = -v;
                col[t] = v;
            }
        }
        float ss = 0.f;
        for (int t = 0; t < T36; ++t) ss += col[t] * col[t];
        float g = sqrtf(ss);
        if (g == 0.f) g = sqrtf((float)T36);
        for (int t = 0; t < T36; ++t) sDloc[t * KP + k] = col[t] / g;
    }
    __syncthreads();

    double acc = 0.0;
    for (int idx = tid; idx < KREAL * KREAL; idx += NTHREADS) {
        const int i = idx / KREAL, j = idx % KREAL;
        float d = 0.f;
        for (int t = 0; t < T36; ++t) d += sDloc[t * KP + i] * sDloc[t * KP + j];
        acc += (double)d * (double)d;
    }
    sred[tid] = acc;
    __syncthreads();
    for (int s = NTHREADS / 2; s > 0; s >>= 1) {
        if (tid < s) sred[tid] += sred[tid + s];
        __syncthreads();
    }
    if (tid == 0) {
        const float fro = (float)sqrt(sred[0]);
        g_consts[0] = 1.f / fro;
        g_consts[1] = 0.1f / fro;
    }
    for (int i = tid; i < T36 * KP; i += NTHREADS) g_D[i] = sDloc[i];
}

// =====================================================================
// Main persistent FISTA kernel
//   SMEM (ull-aligned):
//     sY   [KP][SYS]    y (pair-packed), padded even stride
//     sDtY [KP][SYS]    linv * D^T Y
//     sV   [40][SYS]    V = D @ y intermediate (t padded to 40)
//     sDt2 [KP][TPACK]  D packed by (t,t+1) row pairs, k-major  (phase 1 A)
//     sD   [T36][KP]    D f32 t-major                            (phase 2 A)
// =====================================================================
__global__ void __launch_bounds__(NTHREADS, 1)
dyan_fista_kernel(const float* __restrict__ x, float* __restrict__ out)
{
    extern __shared__ unsigned char smraw[];
    ull*   sY   = (ull*)smraw;                    // KP*SYS
    ull*   sDtY = sY   + KP * SYS;                // KP*SYS
    ull*   sV   = sDtY + KP * SYS;                // 40*SYS
    ull*   sDt2 = sV   + 40 * SYS;                // KP*TPACK
    float* sD   = (float*)(sDt2 + KP * TPACK);    // T36*KP

    const int tid     = threadIdx.x;
    const int colBase = blockIdx.x * NCOL;
    const float linv = g_consts[0];
    const float lam  = g_consts[1];

    // ---- stage D (both layouts) ----
    for (int i = tid; i < T36 * KP; i += NTHREADS) sD[i] = g_D[i];
    for (int i = tid; i < KP * TPACK; i += NTHREADS) {
        const int k = i / TPACK, tp = i % TPACK;
        const int t0 = 2 * tp, t1 = 2 * tp + 1;
        const float d0 = (t0 < T36) ? g_D[t0 * KP + k] : 0.f;
        const float d1 = (t1 < T36) ? g_D[t1 * KP + k] : 0.f;
        sDt2[k * TPACK + tp] = pack2(d0, d1);
    }
    // ---- load Y tile into sV rows 0..35 (pad rows 36..39 zero) ----
    for (int i = tid; i < 40 * NPAIR; i += NTHREADS) {
        const int t = i / NPAIR, p = i % NPAIR;
        ull v = 0ull;
        const int c0 = colBase + 2 * p;
        if (t < T36 && c0 < TOTCOL) {
            const int b = c0 / FDIM, f = c0 % FDIM;
            const float2 yv = *(const float2*)(x + ((size_t)b * T36 + t) * FDIM + f);
            v = pack2(yv.x, yv.y);
        }
        sV[t * SYS + p] = v;
    }
    for (int i = tid; i < KP * SYS; i += NTHREADS) sY[i] = 0ull;
    __syncthreads();

    // ---- phase-2 thread mapping ----
    const int  kt    = tid % 21;          // lane-consecutive within warp
    const int  pt    = tid / 21;          // 0..11 (tid<252), 4 pairs each
    const bool p2act = (tid < 252);

    // ---- DtY = linv * D^T @ Ytile ----
    if (p2act) {
        ull acc[8][4] = {};
        #pragma unroll 4
        for (int kk = 0; kk < T36; ++kk) {
            const float* arow = sD + kk * KP + kt;
            ull ad[8];
            #pragma unroll
            for (int i = 0; i < 8; ++i) ad[i] = dup2(arow[21 * i]);
            const ull* brow = sV + (size_t)kk * SYS + 4 * pt;
            const ulonglong2 b01 = *(const ulonglong2*)(brow);
            const ulonglong2 b23 = *(const ulonglong2*)(brow + 2);
            #pragma unroll
            for (int i = 0; i < 8; ++i) {
                fma2(acc[i][0], ad[i], b01.x);
                fma2(acc[i][1], ad[i], b01.y);
                fma2(acc[i][2], ad[i], b23.x);
                fma2(acc[i][3], ad[i], b23.y);
            }
        }
        #pragma unroll
        for (int i = 0; i < 8; ++i) {
            ull* drow = sDtY + (size_t)(kt + 21 * i) * SYS + 4 * pt;
            #pragma unroll
            for (int j = 0; j < 4; ++j) {
                const float2 s = unpack2(acc[i][j]);
                drow[j] = pack2(s.x * linv, s.y * linv);
            }
        }
    }

    ull xold[8][4] = {};        // x_old in registers, fixed ownership
    float tcur = 1.f;

    // ---- phase-1 thread mapping: 8 warps x 6 pairs; lanes 5tg x 6pl ----
    const int  w     = tid >> 5;
    const int  l     = tid & 31;
    const bool p1act = (l < 30);
    const int  tg    = l / 6;             // 0..4 -> packed rows 4tg..4tg+3
    const int  pl    = l % 6;
    const int  pair1 = 6 * w + pl;

    __syncthreads();

    for (int it = 0; it < NITER; ++it) {
        // ======== phase 1: V = D @ y (packed over (t,t+1) rows) ========
        if (p1act) {
            ull vac[4][2] = {};
            const ull* a0 = sDt2 + 4 * tg;
            const ull* yb = sY + pair1;
            #pragma unroll 7
            for (int kk = 0; kk < KREAL; ++kk) {
                const ulonglong2 a01 = *(const ulonglong2*)(a0 + (size_t)kk * TPACK);
                const ulonglong2 a23 = *(const ulonglong2*)(a0 + (size_t)kk * TPACK + 2);
                const float2 y2 = unpack2(yb[(size_t)kk * SYS]);
                const ull d0 = dup2(y2.x), d1 = dup2(y2.y);
                fma2(vac[0][0], a01.x, d0); fma2(vac[0][1], a01.x, d1);
                fma2(vac[1][0], a01.y, d0); fma2(vac[1][1], a01.y, d1);
                fma2(vac[2][0], a23.x, d0); fma2(vac[2][1], a23.x, d1);
                fma2(vac[3][0], a23.y, d0); fma2(vac[3][1], a23.y, d1);
            }
            #pragma unroll
            for (int p = 0; p < 4; ++p) {
                const int t0 = 2 * (4 * tg + p);
                const float2 c0 = unpack2(vac[p][0]);   // (V[t0], V[t0+1]) col0
                const float2 c1 = unpack2(vac[p][1]);   // col1
                sV[(size_t)t0 * SYS + pair1]       = pack2(c0.x, c1.x);
                sV[(size_t)(t0 + 1) * SYS + pair1] = pack2(c0.y, c1.y);
            }
        }
        __syncthreads();

        // FISTA momentum scalars (identical in every thread)
        const float tnext = 0.5f * (1.f + sqrtf(fmaf(4.f * tcur, tcur, 1.f)));
        const float tt = (tcur - 1.f) / tnext;
        tcur = tnext;

        // ======== phase 2: S = D^T @ V, fused shrink + momentum ========
        if (p2act) {
            ull acc[8][4] = {};
            #pragma unroll 4
            for (int kk = 0; kk < T36; ++kk) {
                const float* arow = sD + kk * KP + kt;
                ull ad[8];
                #pragma unroll
                for (int i = 0; i < 8; ++i) ad[i] = dup2(arow[21 * i]);
                const ull* brow = sV + (size_t)kk * SYS + 4 * pt;
                const ulonglong2 b01 = *(const ulonglong2*)(brow);
                const ulonglong2 b23 = *(const ulonglong2*)(brow + 2);
                #pragma unroll
                for (int i = 0; i < 8; ++i) {
                    fma2(acc[i][0], ad[i], b01.x);
                    fma2(acc[i][1], ad[i], b01.y);
                    fma2(acc[i][2], ad[i], b23.x);
                    fma2(acc[i][3], ad[i], b23.y);
                }
            }
            #pragma unroll
            for (int i = 0; i < 8; ++i) {
                const int k = kt + 21 * i;
                ull* yrow = sY + (size_t)k * SYS + 4 * pt;
                const ull* drow = sDtY + (size_t)k * SYS + 4 * pt;
                const ulonglong2 y01 = *(const ulonglong2*)(yrow);
                const ulonglong2 y23 = *(const ulonglong2*)(yrow + 2);
                const ulonglong2 t01 = *(const ulonglong2*)(drow);
                const ulonglong2 t23 = *(const ulonglong2*)(drow + 2);
                const ull yv[4] = {y01.x, y01.y, y23.x, y23.y};
                const ull dv[4] = {t01.x, t01.y, t23.x, t23.y};
                ull ynew[4];
                #pragma unroll
                for (int j = 0; j < 4; ++j) {
                    const float2 s  = unpack2(acc[i][j]);
                    const float2 y2 = unpack2(yv[j]);
                    const float2 d2 = unpack2(dv[j]);
                    const float r0 = fmaf(-linv, s.x, y2.x) + d2.x;
                    const float r1 = fmaf(-linv, s.y, y2.y) + d2.y;
                    const float x0 = copysignf(fmaxf(fabsf(r0) - lam, 0.f), r0);
                    const float x1 = copysignf(fmaxf(fabsf(r1) - lam, 0.f), r1);
                    const float2 xo = unpack2(xold[i][j]);
                    const float yn0 = fmaf(tt, x0 - xo.x, x0);
                    const float yn1 = fmaf(tt, x1 - xo.y, x1);
                    xold[i][j] = pack2(x0, x1);
                    ynew[j] = pack2(yn0, yn1);
                }
                ulonglong2 w01; w01.x = ynew[0]; w01.y = ynew[1];
                ulonglong2 w23; w23.x = ynew[2]; w23.y = ynew[3];
                *(ulonglong2*)(yrow)     = w01;
                *(ulonglong2*)(yrow + 2) = w23;
            }
        }
        __syncthreads();
    }

    // ---- stage final x through sY, then coalesced global write ----
    if (p2act) {
        #pragma unroll
        for (int i = 0; i < 8; ++i) {
            const int k = kt + 21 * i;
            ull* yrow = sY + (size_t)k * SYS + 4 * pt;
            #pragma unroll
            for (int j = 0; j < 4; ++j) yrow[j] = xold[i][j];
        }
    }
    __syncthreads();

    for (int idx = tid; idx < KREAL * NPAIR; idx += NTHREADS) {
        const int k = idx / NPAIR, p = idx % NPAIR;
        const int c0 = colBase + 2 * p;
        if (c0 < TOTCOL) {
            const int b = c0 / FDIM, f = c0 % FDIM;
            const float2 v = unpack2(sY[(size_t)k * SYS + p]);
            *(float2*)(out + ((size_t)b * KREAL + k) * FDIM + f) = v;
        }
    }
}

// =====================================================================
extern "C" void kernel_launch(void* const* d_in, const int* in_sizes, int n_in,
                              void* d_out, int out_size)
{
    const float* x   = (const float*)d_in[0];
    const float* drr = (const float*)d_in[1];
    const float* dth = (const float*)d_in[2];
    float* out = (float*)d_out;
    (void)in_sizes; (void)n_in; (void)out_size;

    const size_t smem = (size_t)(KP * SYS * 2 + 40 * SYS + KP * TPACK) * sizeof(ull)
                      + (size_t)(T36 * KP) * sizeof(float);   // 201,472 B

    cudaFuncSetAttribute(dyan_fista_kernel,
                         cudaFuncAttributeMaxDynamicSharedMemorySize, (int)smem);

    dyan_setup_kernel<<<1, NTHREADS>>>(drr, dth);

    const int grid = (TOTCOL + NCOL - 1) / NCOL;   // 427
    dyan_fista_kernel<<<grid, NTHREADS, smem>>>(x, out);
}

// round 9
// speedup vs baseline: 1.6624x; 1.0174x over previous
#include <cuda_runtime.h>
#include <math.h>

// DYAN FISTA sparse coding, fully SMEM-resident persistent iteration.
//   x: [2, 36, 20480] f32; Drr/Dtheta: [40] f32; out: [2, 161, 20480] f32
//
// Round-8: 512 threads/CTA (4 warps/SMSP for latency hiding).
//   - phase 2: kt2 = tid%42 (4 k-rows, stride 42) x pt = tid/42 (4 pairs),
//     504 active threads; FMA-floor-bound (~126 cyc/kk).
//   - phase 1 deliberately kept NARROW (240 threads = its crossbar-optimal
//     shape; A-broadcast traffic scales with warp count, so more warps would
//     make it slower). Idle warps wait at the barrier.

#define T36    36
#define TPACK  20      // packed (t,t+1) rows incl pad to t=40
#define KREAL  161
#define KP     168     // padded K (42*4)
#define NPAIR  48      // column pairs per CTA (96 columns)
#define NCOL   96
#define FDIM   20480
#define TOTCOL 40960
#define NITER  100
#define NTHREADS 512
#define SYS    50      // EVEN row stride (ull) -> 16B alignment; 100 words % 32 = 4

typedef unsigned long long ull;

// ---------------- device scratch ----------------
__device__ float g_D[T36 * KP];   // normalized dictionary [t][k], pad cols zero
__device__ float g_consts[2];     // {linv, lam}

// ---------------- packed f32x2 helpers ----------------
__device__ __forceinline__ void fma2(ull &d, ull a, ull b) {
    asm("fma.rn.f32x2 %0, %1, %2, %0;" : "+l"(d) : "l"(a), "l"(b));
}
__device__ __forceinline__ ull dup2(float x) {
    ull r; unsigned u = __float_as_uint(x);
    asm("mov.b64 %0, {%1, %1};" : "=l"(r) : "r"(u));
    return r;
}
__device__ __forceinline__ ull pack2(float a, float b) {
    ull r;
    asm("mov.b64 %0, {%1, %2};" : "=l"(r) : "f"(a), "f"(b));
    return r;
}
__device__ __forceinline__ float2 unpack2(ull v) {
    float2 r;
    asm("mov.b64 {%0, %1}, %2;" : "=f"(r.x), "=f"(r.y) : "l"(v));
    return r;
}

// =====================================================================
// Setup: build normalized dictionary + linv = 1/||D^T D||_F, lam = 0.1*linv
// =====================================================================
#define SETUP_T 256
__global__ void dyan_setup_kernel(const float* __restrict__ Drr,
                                  const float* __restrict__ Dtheta)
{
    __shared__ float  sDloc[T36 * KP];
    __shared__ double sred[SETUP_T];
    const int tid = threadIdx.x;

    for (int i = tid; i < T36 * KP; i += SETUP_T) sDloc[i] = 0.f;
    __syncthreads();

    for (int k = tid; k < KREAL; k += SETUP_T) {
        float col[T36];
        if (k == 0) {
            #pragma unroll
            for (int t = 0; t < T36; ++t) col[t] = 1.f;
        } else {
            const int grp = (k - 1) / 40;      // 0:rc 1:src 2:rs 3:srs
            const int n   = (k - 1) % 40;
            const float r  = Drr[n];
            const float th = Dtheta[n];
            for (int t = 0; t < T36; ++t) {
                float ri   = powf(r, (float)t);
                float base = (grp < 2) ? cosf((float)t * th) : sinf((float)t * th);
                float v = ri * base;
                if ((grp & 1) && (t & 1)) v = -v;
                col[t] = v;
            }
        }
        float ss = 0.f;
        for (int t = 0; t < T36; ++t) ss += col[t] * col[t];
        float g = sqrtf(ss);
        if (g == 0.f) g = sqrtf((float)T36);
        for (int t = 0; t < T36; ++t) sDloc[t * KP + k] = col[t] / g;
    }
    __syncthreads();

    double acc = 0.0;
    for (int idx = tid; idx < KREAL * KREAL; idx += SETUP_T) {
        const int i = idx / KREAL, j = idx % KREAL;
        float d = 0.f;
        for (int t = 0; t < T36; ++t) d += sDloc[t * KP + i] * sDloc[t * KP + j];
        acc += (double)d * (double)d;
    }
    sred[tid] = acc;
    __syncthreads();
    for (int s = SETUP_T / 2; s > 0; s >>= 1) {
        if (tid < s) sred[tid] += sred[tid + s];
        __syncthreads();
    }
    if (tid == 0) {
        const float fro = (float)sqrt(sred[0]);
        g_consts[0] = 1.f / fro;
        g_consts[1] = 0.1f / fro;
    }
    for (int i = tid; i < T36 * KP; i += SETUP_T) g_D[i] = sDloc[i];
}

// =====================================================================
// Main persistent FISTA kernel
//   SMEM (ull-aligned):
//     sY   [KP][SYS]    y (pair-packed), padded even stride
//     sDtY [KP][SYS]    linv * D^T Y
//     sV   [40][SYS]    V = D @ y intermediate (t padded to 40)
//     sDt2 [KP][TPACK]  D packed by (t,t+1) row pairs, k-major  (phase 1 A)
//     sD   [T36][KP]    D f32 t-major                            (phase 2 A)
// =====================================================================
__global__ void __launch_bounds__(NTHREADS, 1)
dyan_fista_kernel(const float* __restrict__ x, float* __restrict__ out)
{
    extern __shared__ unsigned char smraw[];
    ull*   sY   = (ull*)smraw;                    // KP*SYS
    ull*   sDtY = sY   + KP * SYS;                // KP*SYS
    ull*   sV   = sDtY + KP * SYS;                // 40*SYS
    ull*   sDt2 = sV   + 40 * SYS;                // KP*TPACK
    float* sD   = (float*)(sDt2 + KP * TPACK);    // T36*KP

    const int tid     = threadIdx.x;
    const int colBase = blockIdx.x * NCOL;
    const float linv = g_consts[0];
    const float lam  = g_consts[1];

    // ---- stage D (both layouts) ----
    for (int i = tid; i < T36 * KP; i += NTHREADS) sD[i] = g_D[i];
    for (int i = tid; i < KP * TPACK; i += NTHREADS) {
        const int k = i / TPACK, tp = i % TPACK;
        const int t0 = 2 * tp, t1 = 2 * tp + 1;
        const float d0 = (t0 < T36) ? g_D[t0 * KP + k] : 0.f;
        const float d1 = (t1 < T36) ? g_D[t1 * KP + k] : 0.f;
        sDt2[k * TPACK + tp] = pack2(d0, d1);
    }
    // ---- load Y tile into sV rows 0..35 (pad rows 36..39 zero) ----
    for (int i = tid; i < 40 * NPAIR; i += NTHREADS) {
        const int t = i / NPAIR, p = i % NPAIR;
        ull v = 0ull;
        const int c0 = colBase + 2 * p;
        if (t < T36 && c0 < TOTCOL) {
            const int b = c0 / FDIM, f = c0 % FDIM;
            const float2 yv = *(const float2*)(x + ((size_t)b * T36 + t) * FDIM + f);
            v = pack2(yv.x, yv.y);
        }
        sV[t * SYS + p] = v;
    }
    for (int i = tid; i < KP * SYS; i += NTHREADS) sY[i] = 0ull;
    __syncthreads();

    // ---- phase-2 thread mapping: 42 kt-groups x 12 pair-groups ----
    const int  kt2   = tid % 42;          // k = kt2 + 42*i, i<4 (lane-consecutive)
    const int  pt    = tid / 42;          // 0..12; active < 12
    const bool p2act = (pt < 12);

    // ---- DtY = linv * D^T @ Ytile ----
    if (p2act) {
        ull acc[4][4] = {};
        #pragma unroll 4
        for (int kk = 0; kk < T36; ++kk) {
            const float* arow = sD + kk * KP + kt2;
            ull ad[4];
            #pragma unroll
            for (int i = 0; i < 4; ++i) ad[i] = dup2(arow[42 * i]);
            const ull* brow = sV + (size_t)kk * SYS + 4 * pt;
            const ulonglong2 b01 = *(const ulonglong2*)(brow);
            const ulonglong2 b23 = *(const ulonglong2*)(brow + 2);
            #pragma unroll
            for (int i = 0; i < 4; ++i) {
                fma2(acc[i][0], ad[i], b01.x);
                fma2(acc[i][1], ad[i], b01.y);
                fma2(acc[i][2], ad[i], b23.x);
                fma2(acc[i][3], ad[i], b23.y);
            }
        }
        #pragma unroll
        for (int i = 0; i < 4; ++i) {
            ull* drow = sDtY + (size_t)(kt2 + 42 * i) * SYS + 4 * pt;
            #pragma unroll
            for (int j = 0; j < 4; ++j) {
                const float2 s = unpack2(acc[i][j]);
                drow[j] = pack2(s.x * linv, s.y * linv);
            }
        }
    }

    ull xold[4][4] = {};        // x_old in registers, fixed ownership
    float tcur = 1.f;

    // ---- phase-1 thread mapping: 5 row-groups x 48 pairs = 240 threads ----
    // (kept narrow on purpose: A-broadcast crossbar traffic scales with the
    //  number of participating warps; 240 threads is the balanced point)
    const int  pq    = tid % 48;          // column pair
    const int  tc    = tid / 48;          // 0..10; active < 5 -> rows 4tc..4tc+3
    const bool p1act = (tc < 5);

    __syncthreads();

    for (int it = 0; it < NITER; ++it) {
        // ======== phase 1: V = D @ y (packed over (t,t+1) rows) ========
        if (p1act) {
            ull vac[4][2] = {};
            const ull* a0 = sDt2 + 4 * tc;
            const ull* yb = sY + pq;
            #pragma unroll 4
            for (int kk = 0; kk < KREAL; ++kk) {
                const ulonglong2 a01 = *(const ulonglong2*)(a0 + (size_t)kk * TPACK);
                const ulonglong2 a23 = *(const ulonglong2*)(a0 + (size_t)kk * TPACK + 2);
                const float2 y2 = unpack2(yb[(size_t)kk * SYS]);
                const ull d0 = dup2(y2.x), d1 = dup2(y2.y);
                fma2(vac[0][0], a01.x, d0); fma2(vac[0][1], a01.x, d1);
                fma2(vac[1][0], a01.y, d0); fma2(vac[1][1], a01.y, d1);
                fma2(vac[2][0], a23.x, d0); fma2(vac[2][1], a23.x, d1);
                fma2(vac[3][0], a23.y, d0); fma2(vac[3][1], a23.y, d1);
            }
            #pragma unroll
            for (int p = 0; p < 4; ++p) {
                const int t0 = 2 * (4 * tc + p);
                const float2 c0 = unpack2(vac[p][0]);   // (V[t0], V[t0+1]) col0
                const float2 c1 = unpack2(vac[p][1]);   // col1
                sV[(size_t)t0 * SYS + pq]       = pack2(c0.x, c1.x);
                sV[(size_t)(t0 + 1) * SYS + pq] = pack2(c0.y, c1.y);
            }
        }
        __syncthreads();

        // FISTA momentum scalars (identical in every thread)
        const float tnext = 0.5f * (1.f + sqrtf(fmaf(4.f * tcur, tcur, 1.f)));
        const float tt = (tcur - 1.f) / tnext;
        tcur = tnext;

        // ======== phase 2: S = D^T @ V, fused shrink + momentum ========
        if (p2act) {
            ull acc[4][4] = {};
            #pragma unroll 4
            for (int kk = 0; kk < T36; ++kk) {
                const float* arow = sD + kk * KP + kt2;
                ull ad[4];
                #pragma unroll
                for (int i = 0; i < 4; ++i) ad[i] = dup2(arow[42 * i]);
                const ull* brow = sV + (size_t)kk * SYS + 4 * pt;
                const ulonglong2 b01 = *(const ulonglong2*)(brow);
                const ulonglong2 b23 = *(const ulonglong2*)(brow + 2);
                #pragma unroll
                for (int i = 0; i < 4; ++i) {
                    fma2(acc[i][0], ad[i], b01.x);
                    fma2(acc[i][1], ad[i], b01.y);
                    fma2(acc[i][2], ad[i], b23.x);
                    fma2(acc[i][3], ad[i], b23.y);
                }
            }
            #pragma unroll
            for (int i = 0; i < 4; ++i) {
                const int k = kt2 + 42 * i;
                ull* yrow = sY + (size_t)k * SYS + 4 * pt;
                const ull* drow = sDtY + (size_t)k * SYS + 4 * pt;
                const ulonglong2 y01 = *(const ulonglong2*)(yrow);
                const ulonglong2 y23 = *(const ulonglong2*)(yrow + 2);
                const ulonglong2 t01 = *(const ulonglong2*)(drow);
                const ulonglong2 t23 = *(const ulonglong2*)(drow + 2);
                const ull yv[4] = {y01.x, y01.y, y23.x, y23.y};
                const ull dv[4] = {t01.x, t01.y, t23.x, t23.y};
                ull ynew[4];
                #pragma unroll
                for (int j = 0; j < 4; ++j) {
                    const float2 s  = unpack2(acc[i][j]);
                    const float2 y2 = unpack2(yv[j]);
                    const float2 d2 = unpack2(dv[j]);
                    const float r0 = fmaf(-linv, s.x, y2.x) + d2.x;
                    const float r1 = fmaf(-linv, s.y, y2.y) + d2.y;
                    const float x0 = copysignf(fmaxf(fabsf(r0) - lam, 0.f), r0);
                    const float x1 = copysignf(fmaxf(fabsf(r1) - lam, 0.f), r1);
                    const float2 xo = unpack2(xold[i][j]);
                    const float yn0 = fmaf(tt, x0 - xo.x, x0);
                    const float yn1 = fmaf(tt, x1 - xo.y, x1);
                    xold[i][j] = pack2(x0, x1);
                    ynew[j] = pack2(yn0, yn1);
                }
                ulonglong2 w01; w01.x = ynew[0]; w01.y = ynew[1];
                ulonglong2 w23; w23.x = ynew[2]; w23.y = ynew[3];
                *(ulonglong2*)(yrow)     = w01;
                *(ulonglong2*)(yrow + 2) = w23;
            }
        }
        __syncthreads();
    }

    // ---- stage final x through sY, then coalesced global write ----
    if (p2act) {
        #pragma unroll
        for (int i = 0; i < 4; ++i) {
            const int k = kt2 + 42 * i;
            ull* yrow = sY + (size_t)k * SYS + 4 * pt;
            #pragma unroll
            for (int j = 0; j < 4; ++j) yrow[j] = xold[i][j];
        }
    }
    __syncthreads();

    for (int idx = tid; idx < KREAL * NPAIR; idx += NTHREADS) {
        const int k = idx / NPAIR, p = idx % NPAIR;
        const int c0 = colBase + 2 * p;
        if (c0 < TOTCOL) {
            const int b = c0 / FDIM, f = c0 % FDIM;
            const float2 v = unpack2(sY[(size_t)k * SYS + p]);
            *(float2*)(out + ((size_t)b * KREAL + k) * FDIM + f) = v;
        }
    }
}

// =====================================================================
extern "C" void kernel_launch(void* const* d_in, const int* in_sizes, int n_in,
                              void* d_out, int out_size)
{
    const float* x   = (const float*)d_in[0];
    const float* drr = (const float*)d_in[1];
    const float* dth = (const float*)d_in[2];
    float* out = (float*)d_out;
    (void)in_sizes; (void)n_in; (void)out_size;

    const size_t smem = (size_t)(KP * SYS * 2 + 40 * SYS + KP * TPACK) * sizeof(ull)
                      + (size_t)(T36 * KP) * sizeof(float);   // 201,472 B

    cudaFuncSetAttribute(dyan_fista_kernel,
                         cudaFuncAttributeMaxDynamicSharedMemorySize, (int)smem);

    dyan_setup_kernel<<<1, SETUP_T>>>(drr, dth);

    const int grid = (TOTCOL + NCOL - 1) / NCOL;   // 427
    dyan_fista_kernel<<<grid, NTHREADS, smem>>>(x, out);
}

// round 10
// speedup vs baseline: 1.8764x; 1.1287x over previous
#include <cuda_runtime.h>
#include <math.h>

// DYAN FISTA sparse coding, fully SMEM-resident persistent iteration.
//   x: [2, 36, 20480] f32; Drr/Dtheta: [40] f32; out: [2, 161, 20480] f32
//
// Round-9: phase-1 retiled to its FMA floor.
//   - phase 1: 120 threads (5 row-groups x 24 pair-groups), tile = 4 packed
//     (t,t+1) rows x 4 columns -> 16 FFMA2 per kk per thread; A loads hit a
//     single 128B window (1 wf), y is one contiguous LDS.128 (~3 wf).
//     ~19 wf/kk << 30 fma cyc/kk -> FMA-bound (~32 cyc/kk vs ~50 before).
//   - phase 2 unchanged (already at FMA floor).
//   - epilogue r-computation packed with fma.rn.f32x2 / add.rn.f32x2.

#define T36    36
#define TPACK  20      // packed (t,t+1) rows incl pad to t=40
#define KREAL  161
#define KP     168     // padded K (42*4)
#define NPAIR  48      // column pairs per CTA (96 columns)
#define NCOL   96
#define FDIM   20480
#define TOTCOL 40960
#define NITER  100
#define NTHREADS 512
#define SYS    50      // EVEN row stride (ull) -> 16B alignment; 100 words % 32 = 4

typedef unsigned long long ull;

// ---------------- device scratch ----------------
__device__ float g_D[T36 * KP];   // normalized dictionary [t][k], pad cols zero
__device__ float g_consts[2];     // {linv, lam}

// ---------------- packed f32x2 helpers ----------------
__device__ __forceinline__ void fma2(ull &d, ull a, ull b) {
    asm("fma.rn.f32x2 %0, %1, %2, %0;" : "+l"(d) : "l"(a), "l"(b));
}
__device__ __forceinline__ void add2(ull &d, ull a, ull b) {
    asm("add.rn.f32x2 %0, %1, %2;" : "=l"(d) : "l"(a), "l"(b));
}
__device__ __forceinline__ ull dup2(float x) {
    ull r; unsigned u = __float_as_uint(x);
    asm("mov.b64 %0, {%1, %1};" : "=l"(r) : "r"(u));
    return r;
}
__device__ __forceinline__ ull pack2(float a, float b) {
    ull r;
    asm("mov.b64 %0, {%1, %2};" : "=l"(r) : "f"(a), "f"(b));
    return r;
}
__device__ __forceinline__ float2 unpack2(ull v) {
    float2 r;
    asm("mov.b64 {%0, %1}, %2;" : "=f"(r.x), "=f"(r.y) : "l"(v));
    return r;
}

// =====================================================================
// Setup: build normalized dictionary + linv = 1/||D^T D||_F, lam = 0.1*linv
// =====================================================================
#define SETUP_T 256
__global__ void dyan_setup_kernel(const float* __restrict__ Drr,
                                  const float* __restrict__ Dtheta)
{
    __shared__ float  sDloc[T36 * KP];
    __shared__ double sred[SETUP_T];
    const int tid = threadIdx.x;

    for (int i = tid; i < T36 * KP; i += SETUP_T) sDloc[i] = 0.f;
    __syncthreads();

    for (int k = tid; k < KREAL; k += SETUP_T) {
        float col[T36];
        if (k == 0) {
            #pragma unroll
            for (int t = 0; t < T36; ++t) col[t] = 1.f;
        } else {
            const int grp = (k - 1) / 40;      // 0:rc 1:src 2:rs 3:srs
            const int n   = (k - 1) % 40;
            const float r  = Drr[n];
            const float th = Dtheta[n];
            for (int t = 0; t < T36; ++t) {
                float ri   = powf(r, (float)t);
                float base = (grp < 2) ? cosf((float)t * th) : sinf((float)t * th);
                float v = ri * base;
                if ((grp & 1) && (t & 1)) v = -v;
                col[t] = v;
            }
        }
        float ss = 0.f;
        for (int t = 0; t < T36; ++t) ss += col[t] * col[t];
        float g = sqrtf(ss);
        if (g == 0.f) g = sqrtf((float)T36);
        for (int t = 0; t < T36; ++t) sDloc[t * KP + k] = col[t] / g;
    }
    __syncthreads();

    double acc = 0.0;
    for (int idx = tid; idx < KREAL * KREAL; idx += SETUP_T) {
        const int i = idx / KREAL, j = idx % KREAL;
        float d = 0.f;
        for (int t = 0; t < T36; ++t) d += sDloc[t * KP + i] * sDloc[t * KP + j];
        acc += (double)d * (double)d;
    }
    sred[tid] = acc;
    __syncthreads();
    for (int s = SETUP_T / 2; s > 0; s >>= 1) {
        if (tid < s) sred[tid] += sred[tid + s];
        __syncthreads();
    }
    if (tid == 0) {
        const float fro = (float)sqrt(sred[0]);
        g_consts[0] = 1.f / fro;
        g_consts[1] = 0.1f / fro;
    }
    for (int i = tid; i < T36 * KP; i += SETUP_T) g_D[i] = sDloc[i];
}

// =====================================================================
// Main persistent FISTA kernel
//   SMEM (ull-aligned):
//     sY   [KP][SYS]    y (pair-packed), padded even stride
//     sDtY [KP][SYS]    linv * D^T Y
//     sV   [40][SYS]    V = D @ y intermediate (t padded to 40)
//     sDt2 [KP][TPACK]  D packed by (t,t+1) row pairs, k-major  (phase 1 A)
//     sD   [T36][KP]    D f32 t-major                            (phase 2 A)
// =====================================================================
__global__ void __launch_bounds__(NTHREADS, 1)
dyan_fista_kernel(const float* __restrict__ x, float* __restrict__ out)
{
    extern __shared__ unsigned char smraw[];
    ull*   sY   = (ull*)smraw;                    // KP*SYS
    ull*   sDtY = sY   + KP * SYS;                // KP*SYS
    ull*   sV   = sDtY + KP * SYS;                // 40*SYS
    ull*   sDt2 = sV   + 40 * SYS;                // KP*TPACK
    float* sD   = (float*)(sDt2 + KP * TPACK);    // T36*KP

    const int tid     = threadIdx.x;
    const int colBase = blockIdx.x * NCOL;
    const float linv = g_consts[0];
    const float lam  = g_consts[1];

    // ---- stage D (both layouts) ----
    for (int i = tid; i < T36 * KP; i += NTHREADS) sD[i] = g_D[i];
    for (int i = tid; i < KP * TPACK; i += NTHREADS) {
        const int k = i / TPACK, tp = i % TPACK;
        const int t0 = 2 * tp, t1 = 2 * tp + 1;
        const float d0 = (t0 < T36) ? g_D[t0 * KP + k] : 0.f;
        const float d1 = (t1 < T36) ? g_D[t1 * KP + k] : 0.f;
        sDt2[k * TPACK + tp] = pack2(d0, d1);
    }
    // ---- load Y tile into sV rows 0..35 (pad rows 36..39 zero) ----
    for (int i = tid; i < 40 * NPAIR; i += NTHREADS) {
        const int t = i / NPAIR, p = i % NPAIR;
        ull v = 0ull;
        const int c0 = colBase + 2 * p;
        if (t < T36 && c0 < TOTCOL) {
            const int b = c0 / FDIM, f = c0 % FDIM;
            const float2 yv = *(const float2*)(x + ((size_t)b * T36 + t) * FDIM + f);
            v = pack2(yv.x, yv.y);
        }
        sV[t * SYS + p] = v;
    }
    for (int i = tid; i < KP * SYS; i += NTHREADS) sY[i] = 0ull;
    __syncthreads();

    // ---- phase-2 thread mapping: 42 kt-groups x 12 pair-groups ----
    const int  kt2   = tid % 42;          // k = kt2 + 42*i, i<4 (lane-consecutive)
    const int  pt    = tid / 42;          // 0..12; active < 12
    const bool p2act = (pt < 12);

    // ---- DtY = linv * D^T @ Ytile ----
    if (p2act) {
        ull acc[4][4] = {};
        #pragma unroll 4
        for (int kk = 0; kk < T36; ++kk) {
            const float* arow = sD + kk * KP + kt2;
            ull ad[4];
            #pragma unroll
            for (int i = 0; i < 4; ++i) ad[i] = dup2(arow[42 * i]);
            const ull* brow = sV + (size_t)kk * SYS + 4 * pt;
            const ulonglong2 b01 = *(const ulonglong2*)(brow);
            const ulonglong2 b23 = *(const ulonglong2*)(brow + 2);
            #pragma unroll
            for (int i = 0; i < 4; ++i) {
                fma2(acc[i][0], ad[i], b01.x);
                fma2(acc[i][1], ad[i], b01.y);
                fma2(acc[i][2], ad[i], b23.x);
                fma2(acc[i][3], ad[i], b23.y);
            }
        }
        #pragma unroll
        for (int i = 0; i < 4; ++i) {
            ull* drow = sDtY + (size_t)(kt2 + 42 * i) * SYS + 4 * pt;
            #pragma unroll
            for (int j = 0; j < 4; ++j) {
                const float2 s = unpack2(acc[i][j]);
                drow[j] = pack2(s.x * linv, s.y * linv);
            }
        }
    }

    ull xold[4][4] = {};        // x_old in registers, fixed ownership
    float tcur = 1.f;

    // ---- phase-1 thread mapping: 5 row-groups x 24 pair-groups = 120 thr ----
    // tile = 4 packed (t,t+1) rows x 4 columns (pairs 2pg, 2pg+1)
    const int  pg    = tid % 24;
    const int  tc    = tid / 24;          // 0..21; active < 5 -> packed rows 4tc..4tc+3
    const bool p1act = (tc < 5);

    const ull nlinv2 = dup2(-linv);

    __syncthreads();

    for (int it = 0; it < NITER; ++it) {
        // ======== phase 1: V = D @ y  (4 packed rows x 4 cols / thread) ====
        if (p1act) {
            ull vac[4][4] = {};
            const ull* a0 = sDt2 + 4 * tc;
            const ull* yb = sY + 2 * pg;
            #pragma unroll 7
            for (int kk = 0; kk < KREAL; ++kk) {
                const ulonglong2 a01 = *(const ulonglong2*)(a0 + (size_t)kk * TPACK);
                const ulonglong2 a23 = *(const ulonglong2*)(a0 + (size_t)kk * TPACK + 2);
                const ulonglong2 yq  = *(const ulonglong2*)(yb + (size_t)kk * SYS);
                const float2 yA = unpack2(yq.x);     // cols 0,1
                const float2 yB = unpack2(yq.y);     // cols 2,3
                const ull c0 = dup2(yA.x), c1 = dup2(yA.y);
                const ull c2 = dup2(yB.x), c3 = dup2(yB.y);
                fma2(vac[0][0], a01.x, c0); fma2(vac[0][1], a01.x, c1);
                fma2(vac[0][2], a01.x, c2); fma2(vac[0][3], a01.x, c3);
                fma2(vac[1][0], a01.y, c0); fma2(vac[1][1], a01.y, c1);
                fma2(vac[1][2], a01.y, c2); fma2(vac[1][3], a01.y, c3);
                fma2(vac[2][0], a23.x, c0); fma2(vac[2][1], a23.x, c1);
                fma2(vac[2][2], a23.x, c2); fma2(vac[2][3], a23.x, c3);
                fma2(vac[3][0], a23.y, c0); fma2(vac[3][1], a23.y, c1);
                fma2(vac[3][2], a23.y, c2); fma2(vac[3][3], a23.y, c3);
            }
            // repack: vac[p][c] = (V[t0],V[t0+1]) of col c -> row-major stores
            #pragma unroll
            for (int p = 0; p < 4; ++p) {
                const int t0 = 2 * (4 * tc + p);
                const float2 v0 = unpack2(vac[p][0]);
                const float2 v1 = unpack2(vac[p][1]);
                const float2 v2 = unpack2(vac[p][2]);
                const float2 v3 = unpack2(vac[p][3]);
                ulonglong2 r0; r0.x = pack2(v0.x, v1.x); r0.y = pack2(v2.x, v3.x);
                ulonglong2 r1; r1.x = pack2(v0.y, v1.y); r1.y = pack2(v2.y, v3.y);
                *(ulonglong2*)(sV + (size_t)t0 * SYS + 2 * pg)       = r0;
                *(ulonglong2*)(sV + (size_t)(t0 + 1) * SYS + 2 * pg) = r1;
            }
        }
        __syncthreads();

        // FISTA momentum scalars (identical in every thread)
        const float tnext = 0.5f * (1.f + sqrtf(fmaf(4.f * tcur, tcur, 1.f)));
        const float tt = (tcur - 1.f) / tnext;
        tcur = tnext;

        // ======== phase 2: S = D^T @ V, fused shrink + momentum ========
        if (p2act) {
            ull acc[4][4] = {};
            #pragma unroll 4
            for (int kk = 0; kk < T36; ++kk) {
                const float* arow = sD + kk * KP + kt2;
                ull ad[4];
                #pragma unroll
                for (int i = 0; i < 4; ++i) ad[i] = dup2(arow[42 * i]);
                const ull* brow = sV + (size_t)kk * SYS + 4 * pt;
                const ulonglong2 b01 = *(const ulonglong2*)(brow);
                const ulonglong2 b23 = *(const ulonglong2*)(brow + 2);
                #pragma unroll
                for (int i = 0; i < 4; ++i) {
                    fma2(acc[i][0], ad[i], b01.x);
                    fma2(acc[i][1], ad[i], b01.y);
                    fma2(acc[i][2], ad[i], b23.x);
                    fma2(acc[i][3], ad[i], b23.y);
                }
            }
            #pragma unroll
            for (int i = 0; i < 4; ++i) {
                const int k = kt2 + 42 * i;
                ull* yrow = sY + (size_t)k * SYS + 4 * pt;
                const ull* drow = sDtY + (size_t)k * SYS + 4 * pt;
                const ulonglong2 y01 = *(const ulonglong2*)(yrow);
                const ulonglong2 y23 = *(const ulonglong2*)(yrow + 2);
                const ulonglong2 t01 = *(const ulonglong2*)(drow);
                const ulonglong2 t23 = *(const ulonglong2*)(drow + 2);
                const ull yv[4] = {y01.x, y01.y, y23.x, y23.y};
                const ull dv[4] = {t01.x, t01.y, t23.x, t23.y};
                ull ynew[4];
                #pragma unroll
                for (int j = 0; j < 4; ++j) {
                    // r = y - linv*s + dty   (packed)
                    ull r2 = yv[j];
                    fma2(r2, nlinv2, acc[i][j]);
                    add2(r2, r2, dv[j]);
                    const float2 r = unpack2(r2);
                    // softshrink (scalar)
                    const float x0 = copysignf(fmaxf(fabsf(r.x) - lam, 0.f), r.x);
                    const float x1 = copysignf(fmaxf(fabsf(r.y) - lam, 0.f), r.y);
                    // momentum
                    const float2 xo = unpack2(xold[i][j]);
                    const float yn0 = fmaf(tt, x0 - xo.x, x0);
                    const float yn1 = fmaf(tt, x1 - xo.y, x1);
                    xold[i][j] = pack2(x0, x1);
                    ynew[j] = pack2(yn0, yn1);
                }
                ulonglong2 w01; w01.x = ynew[0]; w01.y = ynew[1];
                ulonglong2 w23; w23.x = ynew[2]; w23.y = ynew[3];
                *(ulonglong2*)(yrow)     = w01;
                *(ulonglong2*)(yrow + 2) = w23;
            }
        }
        __syncthreads();
    }

    // ---- stage final x through sY, then coalesced global write ----
    if (p2act) {
        #pragma unroll
        for (int i = 0; i < 4; ++i) {
            const int k = kt2 + 42 * i;
            ull* yrow = sY + (size_t)k * SYS + 4 * pt;
            #pragma unroll
            for (int j = 0; j < 4; ++j) yrow[j] = xold[i][j];
        }
    }
    __syncthreads();

    for (int idx = tid; idx < KREAL * NPAIR; idx += NTHREADS) {
        const int k = idx / NPAIR, p = idx % NPAIR;
        const int c0 = colBase + 2 * p;
        if (c0 < TOTCOL) {
            const int b = c0 / FDIM, f = c0 % FDIM;
            const float2 v = unpack2(sY[(size_t)k * SYS + p]);
            *(float2*)(out + ((size_t)b * KREAL + k) * FDIM + f) = v;
        }
    }
}

// =====================================================================
extern "C" void kernel_launch(void* const* d_in, const int* in_sizes, int n_in,
                              void* d_out, int out_size)
{
    const float* x   = (const float*)d_in[0];
    const float* drr = (const float*)d_in[1];
    const float* dth = (const float*)d_in[2];
    float* out = (float*)d_out;
    (void)in_sizes; (void)n_in; (void)out_size;

    const size_t smem = (size_t)(KP * SYS * 2 + 40 * SYS + KP * TPACK) * sizeof(ull)
                      + (size_t)(T36 * KP) * sizeof(float);   // 201,472 B

    cudaFuncSetAttribute(dyan_fista_kernel,
                         cudaFuncAttributeMaxDynamicSharedMemorySize, (int)smem);

    dyan_setup_kernel<<<1, SETUP_T>>>(drr, dth);

    const int grid = (TOTCOL + NCOL - 1) / NCOL;   // 427
    dyan_fista_kernel<<<grid, NTHREADS, smem>>>(x, out);
}